// round 1
// baseline (speedup 1.0000x reference)
#include <cuda_runtime.h>
#include <cuda_bf16.h>

// TransINT scoring:
//   r  = pos_r[i]  (also used for the negative branch; neg_r is unused)
//   re = heads[rel2head[r]] * rel2mult[r]
//   sub_pos = ent[pos_h] + re - ent[pos_t]
//   sub_neg = ent[neg_h] + re - ent[neg_t]
//   A = bases[r] (2 x 256); ATA (2x2) -> inverse (fallback I/a if det==0)
//   coef = ATA_inv * (A . sub);  proj = sub - A^T coef;  score = ||proj||^2
// out[0:B)   = pos scores, out[B:2B) = neg scores (float32)

#define D 256
#define WARPS_PER_BLOCK 8

__device__ __forceinline__ float warp_allreduce_sum(float v) {
    #pragma unroll
    for (int m = 16; m > 0; m >>= 1)
        v += __shfl_xor_sync(0xffffffffu, v, m);
    return v;
}

__global__ __launch_bounds__(WARPS_PER_BLOCK * 32)
void transint_kernel(const int* __restrict__ pos_h,
                     const int* __restrict__ pos_t,
                     const int* __restrict__ pos_r,
                     const int* __restrict__ neg_h,
                     const int* __restrict__ neg_t,
                     const float* __restrict__ ent_emb,   // E x D
                     const float* __restrict__ heads,     // K x D
                     const float* __restrict__ bases,     // R x 2 x D
                     const int* __restrict__ rel2head,
                     const float* __restrict__ rel2mult,
                     float* __restrict__ out,
                     int B)
{
    const int warp = blockIdx.x * WARPS_PER_BLOCK + (threadIdx.x >> 5);
    if (warp >= B) return;
    const int lane = threadIdx.x & 31;

    // Per-sample indices (uniform across the warp; broadcast loads)
    const int ph = pos_h[warp];
    const int pt = pos_t[warp];
    const int r  = pos_r[warp];
    const int nh = neg_h[warp];
    const int nt = neg_t[warp];
    const int hd = rel2head[r];
    const float mult = rel2mult[r];

    // Each lane owns 8 consecutive dims = 2 float4's at indices 2*lane, 2*lane+1
    const int v0 = 2 * lane;
    const int v1 = 2 * lane + 1;

    const float4* __restrict__ Eph = (const float4*)(ent_emb + (size_t)ph * D);
    const float4* __restrict__ Ept = (const float4*)(ent_emb + (size_t)pt * D);
    const float4* __restrict__ Enh = (const float4*)(ent_emb + (size_t)nh * D);
    const float4* __restrict__ Ent = (const float4*)(ent_emb + (size_t)nt * D);
    const float4* __restrict__ Hd  = (const float4*)(heads   + (size_t)hd * D);
    const float4* __restrict__ A0p = (const float4*)(bases   + (size_t)r * 2 * D);
    const float4* __restrict__ A1p = (const float4*)(bases   + (size_t)r * 2 * D + D);

    // Issue all loads up-front for MLP (cover L2 latency)
    float4 hp0 = Eph[v0], hp1 = Eph[v1];
    float4 tp0 = Ept[v0], tp1 = Ept[v1];
    float4 hn0 = Enh[v0], hn1 = Enh[v1];
    float4 tn0 = Ent[v0], tn1 = Ent[v1];
    float4 re0 = Hd[v0],  re1 = Hd[v1];
    float4 a00 = A0p[v0], a01 = A0p[v1];
    float4 a10 = A1p[v0], a11 = A1p[v1];

    // r_e = head * mult
    re0.x *= mult; re0.y *= mult; re0.z *= mult; re0.w *= mult;
    re1.x *= mult; re1.y *= mult; re1.z *= mult; re1.w *= mult;

    // sub vectors (8 floats each per lane)
    float sp[8], sn[8], A0[8], A1[8];
    {
        const float* hpp = (const float*)&hp0; const float* hpq = (const float*)&hp1;
        const float* tpp = (const float*)&tp0; const float* tpq = (const float*)&tp1;
        const float* hnp = (const float*)&hn0; const float* hnq = (const float*)&hn1;
        const float* tnp = (const float*)&tn0; const float* tnq = (const float*)&tn1;
        const float* rep = (const float*)&re0; const float* req = (const float*)&re1;
        const float* a0p = (const float*)&a00; const float* a0q = (const float*)&a01;
        const float* a1p = (const float*)&a10; const float* a1q = (const float*)&a11;
        #pragma unroll
        for (int i = 0; i < 4; i++) {
            sp[i]     = hpp[i] + rep[i] - tpp[i];
            sp[i + 4] = hpq[i] + req[i] - tpq[i];
            sn[i]     = hnp[i] + rep[i] - tnp[i];
            sn[i + 4] = hnq[i] + req[i] - tnq[i];
            A0[i]     = a0p[i];  A0[i + 4] = a0q[i];
            A1[i]     = a1p[i];  A1[i + 4] = a1q[i];
        }
    }

    // Partial dot products
    float aa = 0.f, ab = 0.f, dd = 0.f;
    float as0p = 0.f, as1p = 0.f, as0n = 0.f, as1n = 0.f;
    #pragma unroll
    for (int i = 0; i < 8; i++) {
        aa   = fmaf(A0[i], A0[i], aa);
        ab   = fmaf(A0[i], A1[i], ab);
        dd   = fmaf(A1[i], A1[i], dd);
        as0p = fmaf(A0[i], sp[i], as0p);
        as1p = fmaf(A1[i], sp[i], as1p);
        as0n = fmaf(A0[i], sn[i], as0n);
        as1n = fmaf(A1[i], sn[i], as1n);
    }

    // Fused butterfly allreduce of 7 scalars
    #pragma unroll
    for (int m = 16; m > 0; m >>= 1) {
        aa   += __shfl_xor_sync(0xffffffffu, aa,   m);
        ab   += __shfl_xor_sync(0xffffffffu, ab,   m);
        dd   += __shfl_xor_sync(0xffffffffu, dd,   m);
        as0p += __shfl_xor_sync(0xffffffffu, as0p, m);
        as1p += __shfl_xor_sync(0xffffffffu, as1p, m);
        as0n += __shfl_xor_sync(0xffffffffu, as0n, m);
        as1n += __shfl_xor_sync(0xffffffffu, as1n, m);
    }

    // 2x2 inverse with det==0 fallback (inv = I / a)
    const float det = aa * dd - ab * ab;
    float c0p, c1p, c0n, c1n;
    if (det != 0.0f) {
        const float inv_det = 1.0f / det;
        c0p = ( dd * as0p - ab * as1p) * inv_det;
        c1p = (-ab * as0p + aa * as1p) * inv_det;
        c0n = ( dd * as0n - ab * as1n) * inv_det;
        c1n = (-ab * as0n + aa * as1n) * inv_det;
    } else {
        const float inv_a = 1.0f / aa;
        c0p = as0p * inv_a; c1p = as1p * inv_a;
        c0n = as0n * inv_a; c1n = as1n * inv_a;
    }

    // Explicit projection residual (matches reference numerics)
    float scp = 0.f, scn = 0.f;
    #pragma unroll
    for (int i = 0; i < 8; i++) {
        const float pp = sp[i] - c0p * A0[i] - c1p * A1[i];
        const float pn = sn[i] - c0n * A0[i] - c1n * A1[i];
        scp = fmaf(pp, pp, scp);
        scn = fmaf(pn, pn, scn);
    }
    scp = warp_allreduce_sum(scp);
    scn = warp_allreduce_sum(scn);

    if (lane == 0) {
        out[warp]     = scp;
        out[B + warp] = scn;
    }
}

extern "C" void kernel_launch(void* const* d_in, const int* in_sizes, int n_in,
                              void* d_out, int out_size) {
    const int*   pos_h    = (const int*)  d_in[0];
    const int*   pos_t    = (const int*)  d_in[1];
    const int*   pos_r    = (const int*)  d_in[2];
    const int*   neg_h    = (const int*)  d_in[3];
    const int*   neg_t    = (const int*)  d_in[4];
    // d_in[5] = neg_r (unused by the reference)
    const float* ent_emb  = (const float*)d_in[6];
    const float* heads    = (const float*)d_in[7];
    const float* bases    = (const float*)d_in[8];
    const int*   rel2head = (const int*)  d_in[9];
    const float* rel2mult = (const float*)d_in[10];
    float* out = (float*)d_out;

    const int B = in_sizes[0];
    const int blocks = (B + WARPS_PER_BLOCK - 1) / WARPS_PER_BLOCK;
    transint_kernel<<<blocks, WARPS_PER_BLOCK * 32>>>(
        pos_h, pos_t, pos_r, neg_h, neg_t,
        ent_emb, heads, bases, rel2head, rel2mult, out, B);
}

// round 2
// speedup vs baseline: 1.1125x; 1.1125x over previous
#include <cuda_runtime.h>
#include <cuda_bf16.h>

// TransINT scoring, single-pass quadratic form:
//   r  = pos_r[i] (neg_r unused by reference)
//   re = heads[rel2head[r]] * rel2mult[r]
//   s_pos = ent[ph] + re - ent[pt];  s_neg = ent[nh] + re - ent[nt]
//   A = bases[r] (2 x 256); c = ATA^{-1} (A.s)
//   exact-solution identity: ||s - A^T c||^2 = s.s - c.(A.s)
// out[0:B) = pos, out[B:2B) = neg (float32)

#define D 256
#define WARPS_PER_BLOCK 8

__global__ __launch_bounds__(WARPS_PER_BLOCK * 32, 5)
void transint_kernel(const int* __restrict__ pos_h,
                     const int* __restrict__ pos_t,
                     const int* __restrict__ pos_r,
                     const int* __restrict__ neg_h,
                     const int* __restrict__ neg_t,
                     const float* __restrict__ ent_emb,   // E x D
                     const float* __restrict__ heads,     // K x D
                     const float* __restrict__ bases,     // R x 2 x D
                     const int* __restrict__ rel2head,
                     const float* __restrict__ rel2mult,
                     float* __restrict__ out,
                     int B)
{
    const int warp = blockIdx.x * WARPS_PER_BLOCK + (threadIdx.x >> 5);
    if (warp >= B) return;
    const int lane = threadIdx.x & 31;

    // Per-sample indices (uniform across warp; broadcast loads)
    const int ph = pos_h[warp];
    const int pt = pos_t[warp];
    const int r  = pos_r[warp];
    const int nh = neg_h[warp];
    const int nt = neg_t[warp];
    const int hd = rel2head[r];
    const float mult = rel2mult[r];

    // Lane owns 8 consecutive dims = 2 float4's
    const int v0 = 2 * lane;
    const int v1 = 2 * lane + 1;

    const float4* __restrict__ Eph = (const float4*)(ent_emb + (size_t)ph * D);
    const float4* __restrict__ Ept = (const float4*)(ent_emb + (size_t)pt * D);
    const float4* __restrict__ Enh = (const float4*)(ent_emb + (size_t)nh * D);
    const float4* __restrict__ Ent = (const float4*)(ent_emb + (size_t)nt * D);
    const float4* __restrict__ Hd  = (const float4*)(heads   + (size_t)hd * D);
    const float4* __restrict__ A0p = (const float4*)(bases   + (size_t)r * 2 * D);
    const float4* __restrict__ A1p = (const float4*)(bases   + (size_t)r * 2 * D + D);

    // All 14 loads issued up-front (MLP covers L2/DRAM latency)
    float4 hp0 = Eph[v0], hp1 = Eph[v1];
    float4 tp0 = Ept[v0], tp1 = Ept[v1];
    float4 hn0 = Enh[v0], hn1 = Enh[v1];
    float4 tn0 = Ent[v0], tn1 = Ent[v1];
    float4 re0 = Hd[v0],  re1 = Hd[v1];
    float4 a00 = A0p[v0], a01 = A0p[v1];
    float4 a10 = A1p[v0], a11 = A1p[v1];

    // 9 streamed accumulators; no second pass over the data
    float aa = 0.f, ab = 0.f, dd = 0.f;
    float as0p = 0.f, as1p = 0.f, ssp = 0.f;
    float as0n = 0.f, as1n = 0.f, ssn = 0.f;

    {
        const float* hpp = (const float*)&hp0; const float* hpq = (const float*)&hp1;
        const float* tpp = (const float*)&tp0; const float* tpq = (const float*)&tp1;
        const float* hnp = (const float*)&hn0; const float* hnq = (const float*)&hn1;
        const float* tnp = (const float*)&tn0; const float* tnq = (const float*)&tn1;
        const float* rep = (const float*)&re0; const float* req = (const float*)&re1;
        const float* a0p = (const float*)&a00; const float* a0q = (const float*)&a01;
        const float* a1p = (const float*)&a10; const float* a1q = (const float*)&a11;
        #pragma unroll
        for (int i = 0; i < 4; i++) {
            // first float4 group
            {
                const float re = rep[i] * mult;
                const float sv = hpp[i] + re - tpp[i];
                const float nv = hnp[i] + re - tnp[i];
                const float A0 = a0p[i], A1 = a1p[i];
                aa   = fmaf(A0, A0, aa);
                ab   = fmaf(A0, A1, ab);
                dd   = fmaf(A1, A1, dd);
                as0p = fmaf(A0, sv, as0p);
                as1p = fmaf(A1, sv, as1p);
                ssp  = fmaf(sv, sv, ssp);
                as0n = fmaf(A0, nv, as0n);
                as1n = fmaf(A1, nv, as1n);
                ssn  = fmaf(nv, nv, ssn);
            }
            // second float4 group
            {
                const float re = req[i] * mult;
                const float sv = hpq[i] + re - tpq[i];
                const float nv = hnq[i] + re - tnq[i];
                const float A0 = a0q[i], A1 = a1q[i];
                aa   = fmaf(A0, A0, aa);
                ab   = fmaf(A0, A1, ab);
                dd   = fmaf(A1, A1, dd);
                as0p = fmaf(A0, sv, as0p);
                as1p = fmaf(A1, sv, as1p);
                ssp  = fmaf(sv, sv, ssp);
                as0n = fmaf(A0, nv, as0n);
                as1n = fmaf(A1, nv, as1n);
                ssn  = fmaf(nv, nv, ssn);
            }
        }
    }

    // Fused butterfly allreduce of 9 scalars
    #pragma unroll
    for (int m = 16; m > 0; m >>= 1) {
        aa   += __shfl_xor_sync(0xffffffffu, aa,   m);
        ab   += __shfl_xor_sync(0xffffffffu, ab,   m);
        dd   += __shfl_xor_sync(0xffffffffu, dd,   m);
        as0p += __shfl_xor_sync(0xffffffffu, as0p, m);
        as1p += __shfl_xor_sync(0xffffffffu, as1p, m);
        ssp  += __shfl_xor_sync(0xffffffffu, ssp,  m);
        as0n += __shfl_xor_sync(0xffffffffu, as0n, m);
        as1n += __shfl_xor_sync(0xffffffffu, as1n, m);
        ssn  += __shfl_xor_sync(0xffffffffu, ssn,  m);
    }

    if (lane == 0) {
        const float det = aa * dd - ab * ab;
        float scp, scn;
        if (det != 0.0f) {
            // exact normal-equation solve -> ||proj||^2 = ss - c . As
            const float inv_det = 1.0f / det;
            const float c0p = ( dd * as0p - ab * as1p) * inv_det;
            const float c1p = (-ab * as0p + aa * as1p) * inv_det;
            const float c0n = ( dd * as0n - ab * as1n) * inv_det;
            const float c1n = (-ab * as0n + aa * as1n) * inv_det;
            scp = ssp - c0p * as0p - c1p * as1p;
            scn = ssn - c0n * as0n - c1n * as1n;
        } else {
            // fallback c = As / aa is NOT the exact solution -> full quadratic
            const float inv_a = 1.0f / aa;
            const float c0p = as0p * inv_a, c1p = as1p * inv_a;
            const float c0n = as0n * inv_a, c1n = as1n * inv_a;
            scp = ssp - 2.0f * (c0p * as0p + c1p * as1p)
                + c0p * c0p * aa + 2.0f * c0p * c1p * ab + c1p * c1p * dd;
            scn = ssn - 2.0f * (c0n * as0n + c1n * as1n)
                + c0n * c0n * aa + 2.0f * c0n * c1n * ab + c1n * c1n * dd;
        }
        out[warp]     = scp;
        out[B + warp] = scn;
    }
}

extern "C" void kernel_launch(void* const* d_in, const int* in_sizes, int n_in,
                              void* d_out, int out_size) {
    const int*   pos_h    = (const int*)  d_in[0];
    const int*   pos_t    = (const int*)  d_in[1];
    const int*   pos_r    = (const int*)  d_in[2];
    const int*   neg_h    = (const int*)  d_in[3];
    const int*   neg_t    = (const int*)  d_in[4];
    // d_in[5] = neg_r (unused by the reference)
    const float* ent_emb  = (const float*)d_in[6];
    const float* heads    = (const float*)d_in[7];
    const float* bases    = (const float*)d_in[8];
    const int*   rel2head = (const int*)  d_in[9];
    const float* rel2mult = (const float*)d_in[10];
    float* out = (float*)d_out;

    const int B = in_sizes[0];
    const int blocks = (B + WARPS_PER_BLOCK - 1) / WARPS_PER_BLOCK;
    transint_kernel<<<blocks, WARPS_PER_BLOCK * 32>>>(
        pos_h, pos_t, pos_r, neg_h, neg_t,
        ent_emb, heads, bases, rel2head, rel2mult, out, B);
}

// round 3
// speedup vs baseline: 1.3372x; 1.2020x over previous
#include <cuda_runtime.h>
#include <cuda_bf16.h>

// TransINT scoring, single-pass quadratic form:
//   re = heads[rel2head[r]] * rel2mult[r]        (r = pos_r; neg_r unused)
//   s_pos = ent[ph] + re - ent[pt];  s_neg = ent[nh] + re - ent[nt]
//   A = bases[r] (2 x 256); c = ATA^{-1} (A.s)
//   exact-solution identity: ||s - A^T c||^2 = s.s - c.(A.s)
// out[0:B) = pos, out[B:2B) = neg (float32)
//
// Lane mapping: lane L owns float4 indices L (dims 4L..4L+3) and L+32
// (dims 512+4L..). Each LDG.128 is a 512B contiguous warp access = 4 L1tex
// wavefronts (minimum), vs 8 for an interleaved mapping.

#define D 256
#define WARPS_PER_BLOCK 8

__global__ __launch_bounds__(WARPS_PER_BLOCK * 32, 5)
void transint_kernel(const int* __restrict__ pos_h,
                     const int* __restrict__ pos_t,
                     const int* __restrict__ pos_r,
                     const int* __restrict__ neg_h,
                     const int* __restrict__ neg_t,
                     const float* __restrict__ ent_emb,   // E x D
                     const float* __restrict__ heads,     // K x D
                     const float* __restrict__ bases,     // R x 2 x D
                     const int* __restrict__ rel2head,
                     const float* __restrict__ rel2mult,
                     float* __restrict__ out,
                     int B)
{
    const int warp = blockIdx.x * WARPS_PER_BLOCK + (threadIdx.x >> 5);
    if (warp >= B) return;
    const int lane = threadIdx.x & 31;

    // Per-sample indices (uniform across warp; broadcast loads)
    const int ph = pos_h[warp];
    const int pt = pos_t[warp];
    const int r  = pos_r[warp];
    const int nh = neg_h[warp];
    const int nt = neg_t[warp];
    const int hd = rel2head[r];
    const float mult = rel2mult[r];

    // Contiguous split: float4 index = lane and lane+32
    const int v0 = lane;
    const int v1 = lane + 32;

    const float4* __restrict__ Eph = (const float4*)(ent_emb + (size_t)ph * D);
    const float4* __restrict__ Ept = (const float4*)(ent_emb + (size_t)pt * D);
    const float4* __restrict__ Enh = (const float4*)(ent_emb + (size_t)nh * D);
    const float4* __restrict__ Ent = (const float4*)(ent_emb + (size_t)nt * D);
    const float4* __restrict__ Hd  = (const float4*)(heads   + (size_t)hd * D);
    const float4* __restrict__ A0p = (const float4*)(bases   + (size_t)r * 2 * D);
    const float4* __restrict__ A1p = (const float4*)(bases   + (size_t)r * 2 * D + D);

    // All 14 loads issued up-front (MLP covers L2/DRAM latency)
    float4 hp0 = Eph[v0], hp1 = Eph[v1];
    float4 tp0 = Ept[v0], tp1 = Ept[v1];
    float4 hn0 = Enh[v0], hn1 = Enh[v1];
    float4 tn0 = Ent[v0], tn1 = Ent[v1];
    float4 re0 = Hd[v0],  re1 = Hd[v1];
    float4 a00 = A0p[v0], a01 = A0p[v1];
    float4 a10 = A1p[v0], a11 = A1p[v1];

    // 9 streamed accumulators; no second pass over the data
    float aa = 0.f, ab = 0.f, dd = 0.f;
    float as0p = 0.f, as1p = 0.f, ssp = 0.f;
    float as0n = 0.f, as1n = 0.f, ssn = 0.f;

    {
        const float* hpp = (const float*)&hp0; const float* hpq = (const float*)&hp1;
        const float* tpp = (const float*)&tp0; const float* tpq = (const float*)&tp1;
        const float* hnp = (const float*)&hn0; const float* hnq = (const float*)&hn1;
        const float* tnp = (const float*)&tn0; const float* tnq = (const float*)&tn1;
        const float* rep = (const float*)&re0; const float* req = (const float*)&re1;
        const float* a0p = (const float*)&a00; const float* a0q = (const float*)&a01;
        const float* a1p = (const float*)&a10; const float* a1q = (const float*)&a11;
        #pragma unroll
        for (int i = 0; i < 4; i++) {
            {
                const float re = rep[i] * mult;
                const float sv = hpp[i] + re - tpp[i];
                const float nv = hnp[i] + re - tnp[i];
                const float A0 = a0p[i], A1 = a1p[i];
                aa   = fmaf(A0, A0, aa);
                ab   = fmaf(A0, A1, ab);
                dd   = fmaf(A1, A1, dd);
                as0p = fmaf(A0, sv, as0p);
                as1p = fmaf(A1, sv, as1p);
                ssp  = fmaf(sv, sv, ssp);
                as0n = fmaf(A0, nv, as0n);
                as1n = fmaf(A1, nv, as1n);
                ssn  = fmaf(nv, nv, ssn);
            }
            {
                const float re = req[i] * mult;
                const float sv = hpq[i] + re - tpq[i];
                const float nv = hnq[i] + re - tnq[i];
                const float A0 = a0q[i], A1 = a1q[i];
                aa   = fmaf(A0, A0, aa);
                ab   = fmaf(A0, A1, ab);
                dd   = fmaf(A1, A1, dd);
                as0p = fmaf(A0, sv, as0p);
                as1p = fmaf(A1, sv, as1p);
                ssp  = fmaf(sv, sv, ssp);
                as0n = fmaf(A0, nv, as0n);
                as1n = fmaf(A1, nv, as1n);
                ssn  = fmaf(nv, nv, ssn);
            }
        }
    }

    // Fused butterfly allreduce of 9 scalars
    #pragma unroll
    for (int m = 16; m > 0; m >>= 1) {
        aa   += __shfl_xor_sync(0xffffffffu, aa,   m);
        ab   += __shfl_xor_sync(0xffffffffu, ab,   m);
        dd   += __shfl_xor_sync(0xffffffffu, dd,   m);
        as0p += __shfl_xor_sync(0xffffffffu, as0p, m);
        as1p += __shfl_xor_sync(0xffffffffu, as1p, m);
        ssp  += __shfl_xor_sync(0xffffffffu, ssp,  m);
        as0n += __shfl_xor_sync(0xffffffffu, as0n, m);
        as1n += __shfl_xor_sync(0xffffffffu, as1n, m);
        ssn  += __shfl_xor_sync(0xffffffffu, ssn,  m);
    }

    if (lane == 0) {
        const float det = aa * dd - ab * ab;
        float scp, scn;
        if (det != 0.0f) {
            // exact normal-equation solve -> ||proj||^2 = ss - c . As
            const float inv_det = 1.0f / det;
            const float c0p = ( dd * as0p - ab * as1p) * inv_det;
            const float c1p = (-ab * as0p + aa * as1p) * inv_det;
            const float c0n = ( dd * as0n - ab * as1n) * inv_det;
            const float c1n = (-ab * as0n + aa * as1n) * inv_det;
            scp = ssp - c0p * as0p - c1p * as1p;
            scn = ssn - c0n * as0n - c1n * as1n;
        } else {
            // fallback c = As / aa is NOT the exact solution -> full quadratic
            const float inv_a = 1.0f / aa;
            const float c0p = as0p * inv_a, c1p = as1p * inv_a;
            const float c0n = as0n * inv_a, c1n = as1n * inv_a;
            scp = ssp - 2.0f * (c0p * as0p + c1p * as1p)
                + c0p * c0p * aa + 2.0f * c0p * c1p * ab + c1p * c1p * dd;
            scn = ssn - 2.0f * (c0n * as0n + c1n * as1n)
                + c0n * c0n * aa + 2.0f * c0n * c1n * ab + c1n * c1n * dd;
        }
        out[warp]     = scp;
        out[B + warp] = scn;
    }
}

extern "C" void kernel_launch(void* const* d_in, const int* in_sizes, int n_in,
                              void* d_out, int out_size) {
    const int*   pos_h    = (const int*)  d_in[0];
    const int*   pos_t    = (const int*)  d_in[1];
    const int*   pos_r    = (const int*)  d_in[2];
    const int*   neg_h    = (const int*)  d_in[3];
    const int*   neg_t    = (const int*)  d_in[4];
    // d_in[5] = neg_r (unused by the reference)
    const float* ent_emb  = (const float*)d_in[6];
    const float* heads    = (const float*)d_in[7];
    const float* bases    = (const float*)d_in[8];
    const int*   rel2head = (const int*)  d_in[9];
    const float* rel2mult = (const float*)d_in[10];
    float* out = (float*)d_out;

    const int B = in_sizes[0];
    const int blocks = (B + WARPS_PER_BLOCK - 1) / WARPS_PER_BLOCK;
    transint_kernel<<<blocks, WARPS_PER_BLOCK * 32>>>(
        pos_h, pos_t, pos_r, neg_h, neg_t,
        ent_emb, heads, bases, rel2head, rel2mult, out, B);
}